// round 2
// baseline (speedup 1.0000x reference)
#include <cuda_runtime.h>
#include <cstddef>

// Scratch: D = dec@W^T + bias (512 x 1024), 2 MB -> stays L2-resident
__device__ float g_D[512 * 1024];

constexpr int BM = 64, BN = 128, BK = 16;
constexpr int KDIM = 512;
constexpr int NT = KDIM / BK;      // 32 k-tiles
constexpr int ASTR = BM + 4;       // 68  (272B rows, 16B aligned)
constexpr int BSTR = BN + 4;       // 132 (528B rows, 16B aligned)

// ---------------------------------------------------------------------------
// Double-buffered NT GEMM mainloop: acc[4][8] += A[64x512] tile @ B[128x512]^T
// 256 threads, micro-tile 4x8. A,B both K-contiguous.
// ---------------------------------------------------------------------------
__device__ __forceinline__ void mainloop(
    const float* __restrict__ A, const float* __restrict__ B,
    int row0, int col0, int tid,
    float (*As)[BK][ASTR], float (*Bs)[BK][BSTR],
    float acc[4][8], int tx, int ty)
{
    const int sr  = tid >> 2;          // 0..63
    const int skq = (tid & 3) * 4;     // 0,4,8,12

    const float* aptr = A + (size_t)(row0 + sr) * KDIM + skq;
    const float* bptr = B + (size_t)(col0 + sr) * KDIM + skq;

    float4 pa  = *(const float4*)aptr;
    float4 pb0 = *(const float4*)bptr;
    float4 pb1 = *(const float4*)(bptr + 64 * KDIM);

    // stage tile 0 into buffer 0
    As[0][skq + 0][sr] = pa.x;  As[0][skq + 1][sr] = pa.y;
    As[0][skq + 2][sr] = pa.z;  As[0][skq + 3][sr] = pa.w;
    Bs[0][skq + 0][sr] = pb0.x; Bs[0][skq + 1][sr] = pb0.y;
    Bs[0][skq + 2][sr] = pb0.z; Bs[0][skq + 3][sr] = pb0.w;
    Bs[0][skq + 0][sr + 64] = pb1.x; Bs[0][skq + 1][sr + 64] = pb1.y;
    Bs[0][skq + 2][sr + 64] = pb1.z; Bs[0][skq + 3][sr + 64] = pb1.w;
    __syncthreads();

    int buf = 0;
    for (int kt = 0; kt < NT; kt++) {
        const bool more = (kt + 1 < NT);
        if (more) {                      // issue next tile's global loads early
            aptr += BK; bptr += BK;
            pa  = *(const float4*)aptr;
            pb0 = *(const float4*)bptr;
            pb1 = *(const float4*)(bptr + 64 * KDIM);
        }

#pragma unroll
        for (int kk = 0; kk < BK - 1; kk++) {
            float4 ra  = *(const float4*)&As[buf][kk][ty * 4];
            float4 rb0 = *(const float4*)&Bs[buf][kk][tx * 8];
            float4 rb1 = *(const float4*)&Bs[buf][kk][tx * 8 + 4];
            float a4[4] = {ra.x, ra.y, ra.z, ra.w};
            float b8[8] = {rb0.x, rb0.y, rb0.z, rb0.w, rb1.x, rb1.y, rb1.z, rb1.w};
#pragma unroll
            for (int i = 0; i < 4; i++)
#pragma unroll
                for (int j = 0; j < 8; j++)
                    acc[i][j] += a4[i] * b8[j];
        }

        if (more) {                      // fill other buffer while tail computes
            const int nb = buf ^ 1;
            As[nb][skq + 0][sr] = pa.x;  As[nb][skq + 1][sr] = pa.y;
            As[nb][skq + 2][sr] = pa.z;  As[nb][skq + 3][sr] = pa.w;
            Bs[nb][skq + 0][sr] = pb0.x; Bs[nb][skq + 1][sr] = pb0.y;
            Bs[nb][skq + 2][sr] = pb0.z; Bs[nb][skq + 3][sr] = pb0.w;
            Bs[nb][skq + 0][sr + 64] = pb1.x; Bs[nb][skq + 1][sr + 64] = pb1.y;
            Bs[nb][skq + 2][sr + 64] = pb1.z; Bs[nb][skq + 3][sr + 64] = pb1.w;
        }

        {   // last kk
            const int kk = BK - 1;
            float4 ra  = *(const float4*)&As[buf][kk][ty * 4];
            float4 rb0 = *(const float4*)&Bs[buf][kk][tx * 8];
            float4 rb1 = *(const float4*)&Bs[buf][kk][tx * 8 + 4];
            float a4[4] = {ra.x, ra.y, ra.z, ra.w};
            float b8[8] = {rb0.x, rb0.y, rb0.z, rb0.w, rb1.x, rb1.y, rb1.z, rb1.w};
#pragma unroll
            for (int i = 0; i < 4; i++)
#pragma unroll
                for (int j = 0; j < 8; j++)
                    acc[i][j] += a4[i] * b8[j];
        }
        __syncthreads();
        buf ^= 1;
    }
}

// ---------------------------------------------------------------------------
// D = dec(512x512) @ W^T + bias   -> grid (8, 8) = 64 blocks
// ---------------------------------------------------------------------------
__global__ void __launch_bounds__(256, 2)
dgemm_kernel(const float* __restrict__ dec, const float* __restrict__ W,
             const float* __restrict__ bias, float* __restrict__ D)
{
    __shared__ float As[2][BK][ASTR];
    __shared__ float Bs[2][BK][BSTR];
    const int tid = threadIdx.x;
    const int tx = tid & 15, ty = tid >> 4;
    const int row0 = blockIdx.y * BM, col0 = blockIdx.x * BN;

    float acc[4][8] = {};
    mainloop(dec, W, row0, col0, tid, As, Bs, acc, tx, ty);

    float4 bias0 = *(const float4*)(bias + col0 + tx * 8);
    float4 bias1 = *(const float4*)(bias + col0 + tx * 8 + 4);
#pragma unroll
    for (int i = 0; i < 4; i++) {
        const int r = row0 + ty * 4 + i;
        float* dst = D + (size_t)r * 1024 + col0 + tx * 8;
        float4 v0 = make_float4(acc[i][0] + bias0.x, acc[i][1] + bias0.y,
                                acc[i][2] + bias0.z, acc[i][3] + bias0.w);
        float4 v1 = make_float4(acc[i][4] + bias1.x, acc[i][5] + bias1.y,
                                acc[i][6] + bias1.z, acc[i][7] + bias1.w);
        *(float4*)dst       = v0;
        *(float4*)(dst + 4) = v1;
    }
}

// ---------------------------------------------------------------------------
// Fused: compute E-tile = enc(64x512)@W^T in regs, then stream
// out[b,t,u,v] = Etile + D[b,u,v] for all 64 u.  grid (8, 32) = 256 blocks.
// out linear index = (r*64 + u)*1024 + v with r = b*256+t the global enc row.
// ---------------------------------------------------------------------------
__global__ void __launch_bounds__(256, 2)
fused_kernel(const float* __restrict__ enc, const float* __restrict__ W,
             const float* __restrict__ D, float* __restrict__ out)
{
    __shared__ float As[2][BK][ASTR];
    __shared__ float Bs[2][BK][BSTR];
    const int tid = threadIdx.x;
    const int tx = tid & 15, ty = tid >> 4;
    const int row0 = blockIdx.y * BM;       // global enc row (no b straddle: 64|256)
    const int col0 = blockIdx.x * BN;

    float acc[4][8] = {};
    mainloop(enc, W, row0, col0, tid, As, Bs, acc, tx, ty);

    const int b = row0 >> 8;
    const float4* Dp = (const float4*)(D + (size_t)b * 64 * 1024)
                       + (col0 >> 2) + tx * 2;           // advance 256 per u
    float* obase = out + ((size_t)(row0 + ty * 4) * 64) * 1024 + col0 + tx * 8;

    for (int u = 0; u < 64; u++) {
        float4 d0 = __ldg(Dp);
        float4 d1 = __ldg(Dp + 1);
        Dp += 256;
        float* o = obase + (size_t)u * 1024;
#pragma unroll
        for (int i = 0; i < 4; i++) {
            float4 v0 = make_float4(acc[i][0] + d0.x, acc[i][1] + d0.y,
                                    acc[i][2] + d0.z, acc[i][3] + d0.w);
            float4 v1 = make_float4(acc[i][4] + d1.x, acc[i][5] + d1.y,
                                    acc[i][6] + d1.z, acc[i][7] + d1.w);
            float4* op = (float4*)(o + (size_t)i * 64 * 1024);
            __stcs(op,     v0);   // streaming store: don't thrash L2 (D lives there)
            __stcs(op + 1, v1);
        }
    }
}

// ---------------------------------------------------------------------------
extern "C" void kernel_launch(void* const* d_in, const int* in_sizes, int n_in,
                              void* d_out, int out_size) {
    const float* enc  = (const float*)d_in[0];  // (8,256,512)
    const float* dec  = (const float*)d_in[1];  // (8,64,512)
    const float* W    = (const float*)d_in[2];  // (1024,512)
    const float* bias = (const float*)d_in[3];  // (1024,)
    float* out = (float*)d_out;                 // (8,256,64,1024)

    float* D;
    cudaGetSymbolAddress((void**)&D, g_D);

    dgemm_kernel<<<dim3(1024 / BN, 512 / BM), 256>>>(dec, W, bias, D);
    fused_kernel<<<dim3(1024 / BN, 2048 / BM), 256>>>(enc, W, D, out);
}

// round 3
// speedup vs baseline: 2.9384x; 2.9384x over previous
#include <cuda_runtime.h>
#include <cstdint>
#include <cstddef>

// Scratch: E = enc@W^T (2048x1024), D = dec@W^T + bias (512x1024)
__device__ float g_E[2048 * 1024];
__device__ float g_D[512 * 1024];

constexpr int KDIM = 512, NDIM = 1024;
constexpr int BM = 128, BN = 128, BK = 32;
constexpr int NKT = KDIM / BK;        // 16 k-tiles
constexpr int STR = 136;              // padded smem row stride (bank-conflict-free)

__device__ __forceinline__ uint32_t f2tf32(float x) {
    uint32_t r;
    asm("cvt.rna.tf32.f32 %0, %1;" : "=r"(r) : "f"(x));
    return r;
}

__device__ __forceinline__ void mma_tf32(float* c, const uint32_t* a, const uint32_t* b) {
    asm volatile(
        "mma.sync.aligned.m16n8k8.row.col.f32.tf32.tf32.f32 "
        "{%0,%1,%2,%3}, {%4,%5,%6,%7}, {%8,%9}, {%0,%1,%2,%3};\n"
        : "+f"(c[0]), "+f"(c[1]), "+f"(c[2]), "+f"(c[3])
        : "r"(a[0]), "r"(a[1]), "r"(a[2]), "r"(a[3]), "r"(b[0]), "r"(b[1]));
}

// ---------------------------------------------------------------------------
// tf32 tensor-core NT GEMM producing both E and D in one launch.
// grid = (NDIM/BN = 8, 20): blockIdx.y < 16 -> E rows (enc), else D rows (dec, +bias).
// Block 128x128xK, 8 warps in 2x4 layout, warp tile 64x32, mma m16n8k8.
// ---------------------------------------------------------------------------
__global__ void __launch_bounds__(256)
gemm_tf32(const float* __restrict__ enc, const float* __restrict__ dec,
          const float* __restrict__ W, const float* __restrict__ bias,
          float* __restrict__ E, float* __restrict__ D)
{
    __shared__ uint32_t As[BK][STR];
    __shared__ uint32_t Bs[BK][STR];

    const int tid  = threadIdx.x;
    const int col0 = blockIdx.x * BN;
    const bool isE = (blockIdx.y < 16);
    const int row0 = isE ? blockIdx.y * BM : (blockIdx.y - 16) * BM;
    const float* A = isE ? enc : dec;
    float* C       = isE ? g_E : g_D;   // device globals directly addressable

    // Staging: 2 threads per row, each covers 16 consecutive k (4 float4)
    const int arow = tid >> 1;
    const int kh   = (tid & 1) * 16;
    const float* aptr = A + (size_t)(row0 + arow) * KDIM + kh;
    const float* bptr = W + (size_t)(col0 + arow) * KDIM + kh;

    const int lane = tid & 31, warp = tid >> 5;
    const int g = lane >> 2, tig = lane & 3;
    const int wm = (warp >> 2) * 64, wn = (warp & 3) * 32;

    float acc[4][4][4];
#pragma unroll
    for (int mf = 0; mf < 4; mf++)
#pragma unroll
        for (int nf = 0; nf < 4; nf++)
#pragma unroll
            for (int i = 0; i < 4; i++) acc[mf][nf][i] = 0.f;

    float4 pa[4], pb[4];
#pragma unroll
    for (int j = 0; j < 4; j++) {
        pa[j] = *(const float4*)(aptr + j * 4);
        pb[j] = *(const float4*)(bptr + j * 4);
    }

    for (int kt = 0; kt < NKT; kt++) {
        // stage prefetched tile into smem with tf32 rounding
#pragma unroll
        for (int j = 0; j < 4; j++) {
            As[kh + j * 4 + 0][arow] = f2tf32(pa[j].x);
            As[kh + j * 4 + 1][arow] = f2tf32(pa[j].y);
            As[kh + j * 4 + 2][arow] = f2tf32(pa[j].z);
            As[kh + j * 4 + 3][arow] = f2tf32(pa[j].w);
            Bs[kh + j * 4 + 0][arow] = f2tf32(pb[j].x);
            Bs[kh + j * 4 + 1][arow] = f2tf32(pb[j].y);
            Bs[kh + j * 4 + 2][arow] = f2tf32(pb[j].z);
            Bs[kh + j * 4 + 3][arow] = f2tf32(pb[j].w);
        }
        __syncthreads();

        if (kt + 1 < NKT) {            // prefetch next tile (latency hidden by mma)
            aptr += BK; bptr += BK;
#pragma unroll
            for (int j = 0; j < 4; j++) {
                pa[j] = *(const float4*)(aptr + j * 4);
                pb[j] = *(const float4*)(bptr + j * 4);
            }
        }

#pragma unroll
        for (int ks = 0; ks < 4; ks++) {
            const int k8 = ks * 8;
            uint32_t af[4][4], bf[4][2];
#pragma unroll
            for (int mf = 0; mf < 4; mf++) {
                const int m = wm + mf * 16 + g;
                af[mf][0] = As[k8 + tig][m];
                af[mf][1] = As[k8 + tig][m + 8];
                af[mf][2] = As[k8 + tig + 4][m];
                af[mf][3] = As[k8 + tig + 4][m + 8];
            }
#pragma unroll
            for (int nf = 0; nf < 4; nf++) {
                const int n = wn + nf * 8 + g;
                bf[nf][0] = Bs[k8 + tig][n];
                bf[nf][1] = Bs[k8 + tig + 4][n];
            }
#pragma unroll
            for (int mf = 0; mf < 4; mf++)
#pragma unroll
                for (int nf = 0; nf < 4; nf++)
                    mma_tf32(acc[mf][nf], af[mf], bf[nf]);
        }
        __syncthreads();
    }

    // epilogue: C[row][col] (+ bias for D part)
    float2 bv[4];
#pragma unroll
    for (int nf = 0; nf < 4; nf++) {
        if (isE) bv[nf] = make_float2(0.f, 0.f);
        else     bv[nf] = *(const float2*)(bias + col0 + wn + nf * 8 + tig * 2);
    }
#pragma unroll
    for (int mf = 0; mf < 4; mf++) {
        const int r = row0 + wm + mf * 16 + g;
#pragma unroll
        for (int nf = 0; nf < 4; nf++) {
            const int c = col0 + wn + nf * 8 + tig * 2;
            float2 v0 = make_float2(acc[mf][nf][0] + bv[nf].x,
                                    acc[mf][nf][1] + bv[nf].y);
            float2 v1 = make_float2(acc[mf][nf][2] + bv[nf].x,
                                    acc[mf][nf][3] + bv[nf].y);
            *(float2*)(C + (size_t)r * NDIM + c)       = v0;
            *(float2*)(C + (size_t)(r + 8) * NDIM + c) = v1;
        }
    }
}

// ---------------------------------------------------------------------------
// Broadcast add: out[b,t,u,v] = E[b*256+t, v] + D[b*64+u, v]
// 512 blocks x 256 threads; each block: one (b, 4-row t-tile), full 1024-wide
// v rows (4 KB contiguous stores). E rows in regs, D rows stream from L2.
// ---------------------------------------------------------------------------
constexpr int TT = 4;

__global__ void __launch_bounds__(256)
bcast_add(const float* __restrict__ E, const float* __restrict__ D,
          float* __restrict__ out)
{
    const int tile = blockIdx.x;            // 0..511
    const int b    = tile / (256 / TT);     // 0..7
    const int t0   = (tile % (256 / TT)) * TT;
    const int v4   = threadIdx.x;

    const float4* E4 = (const float4*)E;
    const float4* D4 = (const float4*)D;
    float4*       O4 = (float4*)out;

    float4 e[TT];
#pragma unroll
    for (int i = 0; i < TT; i++)
        e[i] = E4[(size_t)(b * 256 + t0 + i) * 256 + v4];

    const size_t base = ((size_t)(b * 256 + t0) * 64) * 256 + v4;

    for (int u = 0; u < 64; u++) {
        float4 d = D4[(size_t)(b * 64 + u) * 256 + v4];
        size_t ou = base + (size_t)u * 256;
#pragma unroll
        for (int i = 0; i < TT; i++) {
            float4 r = make_float4(e[i].x + d.x, e[i].y + d.y,
                                   e[i].z + d.z, e[i].w + d.w);
            O4[ou + (size_t)i * 64 * 256] = r;
        }
    }
}

// ---------------------------------------------------------------------------
extern "C" void kernel_launch(void* const* d_in, const int* in_sizes, int n_in,
                              void* d_out, int out_size) {
    const float* enc  = (const float*)d_in[0];  // (8,256,512)
    const float* dec  = (const float*)d_in[1];  // (8,64,512)
    const float* W    = (const float*)d_in[2];  // (1024,512)
    const float* bias = (const float*)d_in[3];  // (1024,)
    float* out = (float*)d_out;                 // (8,256,64,1024)

    float *E, *D;
    cudaGetSymbolAddress((void**)&E, g_E);
    cudaGetSymbolAddress((void**)&D, g_D);

    gemm_tf32<<<dim3(NDIM / BN, 20), 256>>>(enc, dec, W, bias, E, D);
    bcast_add<<<512, 256>>>(E, D, out);
}